// round 2
// baseline (speedup 1.0000x reference)
#include <cuda_runtime.h>
#include <cuda_bf16.h>

#define RES   1024
#define FEAT  12
#define NCB   32
#define HIMG  1080
#define WIMG  1920
#define NPIX  (HIMG*WIMG)
#define NTHREADS 256

__device__ __forceinline__ void load12(const float* __restrict__ p, float* dst) {
    float4 a = *(const float4*)(p);
    float4 b = *(const float4*)(p + 4);
    float4 c = *(const float4*)(p + 8);
    dst[0]=a.x; dst[1]=a.y; dst[2]=a.z;  dst[3]=a.w;
    dst[4]=b.x; dst[5]=b.y; dst[6]=b.z;  dst[7]=b.w;
    dst[8]=c.x; dst[9]=c.y; dst[10]=c.z; dst[11]=c.w;
}

__global__ __launch_bounds__(NTHREADS)
void sky_kernel(const float* __restrict__ rays,
                const int* __restrict__ mask,
                const float* __restrict__ cube,
                const float* __restrict__ cbk,
                const float* __restrict__ gW1, const float* __restrict__ gb1,
                const float* __restrict__ gW2, const float* __restrict__ gb2,
                const float* __restrict__ gW3, const float* __restrict__ gb3,
                float* __restrict__ out)
{
    __shared__ float sCB[NCB*FEAT];
    __shared__ float sC2[NCB];
    __shared__ float sW1[15*32];
    __shared__ float sB1[32];
    __shared__ float sW2[32*32];
    __shared__ float sB2[32];
    __shared__ float sW3[32*3];
    __shared__ float sB3[3];

    const int tid = threadIdx.x;
    for (int i = tid; i < NCB*FEAT; i += NTHREADS) sCB[i] = cbk[i];
    for (int i = tid; i < 15*32;    i += NTHREADS) sW1[i] = gW1[i];
    for (int i = tid; i < 32*32;    i += NTHREADS) sW2[i] = gW2[i];
    for (int i = tid; i < 32*3;     i += NTHREADS) sW3[i] = gW3[i];
    if (tid < 32) { sB1[tid] = gb1[tid]; sB2[tid] = gb2[tid]; }
    if (tid < 3)  sB3[tid] = gb3[tid];
    if (tid < NCB) {
        float a = 0.f;
        #pragma unroll
        for (int k = 0; k < FEAT; k++) { float c = cbk[tid*FEAT + k]; a += c*c; }
        sC2[tid] = a;
    }
    __syncthreads();

    const int pix = blockIdx.x * NTHREADS + tid;
    if (pix >= NPIX) return;

    if (mask[pix] == 0) {
        out[pix]          = 0.f;
        out[NPIX + pix]   = 0.f;
        out[2*NPIX + pix] = 0.f;
        return;
    }

    const float x = rays[3*pix+0], y = rays[3*pix+1], z = rays[3*pix+2];
    const float ax = fabsf(x), ay = fabsf(y), az = fabsf(z);
    const bool is_x = (ax >= ay) && (ax >= az);
    const bool is_y = (!is_x) && (ay >= az);

    int face; float ma, u, v;
    if (is_x)       { face = (x >= 0.f) ? 0 : 1; ma = ax; u = (x >= 0.f) ? -z : z; v = -y; }
    else if (is_y)  { face = (y >= 0.f) ? 2 : 3; ma = ay; u = x; v = (y >= 0.f) ? z : -z; }
    else            { face = (z >= 0.f) ? 4 : 5; ma = az; u = (z >= 0.f) ? x : -x; v = -y; }

    const float denom = ma + 1e-9f;
    const float sC = (u/denom + 1.f) * 0.5f * (float)RES - 0.5f;
    const float tC = (v/denom + 1.f) * 0.5f * (float)RES - 0.5f;
    const float fs = floorf(sC), ft = floorf(tC);
    const float fx = sC - fs, fy = tC - ft;
    int x0 = (int)fs; x0 = max(0, min(x0, RES-1));
    const int x1 = min(x0+1, RES-1);
    int y0 = (int)ft; y0 = max(0, min(y0, RES-1));
    const int y1 = min(y0+1, RES-1);

    const float* __restrict__ fb = cube + (size_t)face * (size_t)(RES*RES*FEAT);

    float feat[FEAT], tmp[FEAT], bot[FEAT];
    load12(fb + ((size_t)y0*RES + x0)*FEAT, feat);
    load12(fb + ((size_t)y0*RES + x1)*FEAT, tmp);
    #pragma unroll
    for (int k = 0; k < FEAT; k++) feat[k] = feat[k]*(1.f-fx) + tmp[k]*fx;
    load12(fb + ((size_t)y1*RES + x0)*FEAT, bot);
    load12(fb + ((size_t)y1*RES + x1)*FEAT, tmp);
    #pragma unroll
    for (int k = 0; k < FEAT; k++) bot[k] = bot[k]*(1.f-fx) + tmp[k]*fx;
    #pragma unroll
    for (int k = 0; k < FEAT; k++) feat[k] = feat[k]*(1.f-fy) + bot[k]*fy;

    // nearest codebook (first-min-wins to match jnp.argmin)
    float f2 = 0.f;
    #pragma unroll
    for (int k = 0; k < FEAT; k++) f2 += feat[k]*feat[k];
    int best = 0;
    float bestd = 3.4e38f;
    #pragma unroll 4
    for (int c = 0; c < NCB; c++) {
        float dot = 0.f;
        #pragma unroll
        for (int k = 0; k < FEAT; k++) dot += feat[k]*sCB[c*FEAT + k];
        const float d2 = f2 - 2.f*dot + sC2[c];
        if (d2 < bestd) { bestd = d2; best = c; }
    }

    // straight-through: q = feat + (cb[best] - feat)
    float in[15];
    #pragma unroll
    for (int k = 0; k < FEAT; k++) in[k] = feat[k] + (sCB[best*FEAT + k] - feat[k]);
    in[12] = x; in[13] = y; in[14] = z;

    // MLP layer 1: 15 -> 32, relu
    float h[32];
    #pragma unroll
    for (int j = 0; j < 32; j++) h[j] = sB1[j];
    #pragma unroll
    for (int k = 0; k < 15; k++) {
        const float iv = in[k];
        #pragma unroll
        for (int j = 0; j < 32; j++) h[j] += iv * sW1[k*32 + j];
    }
    #pragma unroll
    for (int j = 0; j < 32; j++) h[j] = fmaxf(h[j], 0.f);

    // MLP layer 2: 32 -> 32, relu
    float h2[32];
    #pragma unroll
    for (int j = 0; j < 32; j++) h2[j] = sB2[j];
    #pragma unroll
    for (int k = 0; k < 32; k++) {
        const float iv = h[k];
        #pragma unroll
        for (int j = 0; j < 32; j++) h2[j] += iv * sW2[k*32 + j];
    }
    #pragma unroll
    for (int j = 0; j < 32; j++) h2[j] = fmaxf(h2[j], 0.f);

    // MLP layer 3: 32 -> 3, sigmoid
    float r[3];
    #pragma unroll
    for (int c = 0; c < 3; c++) r[c] = sB3[c];
    #pragma unroll
    for (int k = 0; k < 32; k++) {
        const float iv = h2[k];
        #pragma unroll
        for (int c = 0; c < 3; c++) r[c] += iv * sW3[k*3 + c];
    }
    #pragma unroll
    for (int c = 0; c < 3; c++) {
        float s = 1.f / (1.f + expf(-r[c]));
        s = fminf(fmaxf(s, 0.f), 1.f);
        out[c*NPIX + pix] = s;
    }
}

extern "C" void kernel_launch(void* const* d_in, const int* in_sizes, int n_in,
                              void* d_out, int out_size)
{
    const float* rays = (const float*)d_in[0];
    const int*   mask = (const int*)d_in[1];
    const float* cube = (const float*)d_in[2];
    const float* cbk  = (const float*)d_in[3];
    const float* W1   = (const float*)d_in[4];
    const float* b1   = (const float*)d_in[5];
    const float* W2   = (const float*)d_in[6];
    const float* b2   = (const float*)d_in[7];
    const float* W3   = (const float*)d_in[8];
    const float* b3   = (const float*)d_in[9];
    float* out = (float*)d_out;

    const int blocks = (NPIX + NTHREADS - 1) / NTHREADS;
    sky_kernel<<<blocks, NTHREADS>>>(rays, mask, cube, cbk,
                                     W1, b1, W2, b2, W3, b3, out);
}

// round 3
// speedup vs baseline: 1.3908x; 1.3908x over previous
#include <cuda_runtime.h>
#include <cuda_bf16.h>

#define RES   1024
#define FEAT  12
#define NCB   32
#define HIMG  1080
#define WIMG  1920
#define NPIX  (HIMG*WIMG)
#define NTHREADS 256

__constant__ float cW1[15*32];
__constant__ float cB1[32];
__constant__ float cW2[32*32];
__constant__ float cB2[32];
__constant__ float cW3[32*3];
__constant__ float cB3[3];
__constant__ float cCB[NCB*FEAT];
__constant__ float cC2[NCB];

__device__ float g_c2[NCB];

__global__ void c2_kernel(const float* __restrict__ cbk) {
    int c = threadIdx.x;
    if (c < NCB) {
        float a = 0.f;
        #pragma unroll
        for (int k = 0; k < FEAT; k++) { float v = cbk[c*FEAT + k]; a += v*v; }
        g_c2[c] = a;
    }
}

__device__ __forceinline__ void load12(const float* __restrict__ p, float* dst) {
    float4 a = *(const float4*)(p);
    float4 b = *(const float4*)(p + 4);
    float4 c = *(const float4*)(p + 8);
    dst[0]=a.x; dst[1]=a.y; dst[2]=a.z;  dst[3]=a.w;
    dst[4]=b.x; dst[5]=b.y; dst[6]=b.z;  dst[7]=b.w;
    dst[8]=c.x; dst[9]=c.y; dst[10]=c.z; dst[11]=c.w;
}

__global__ __launch_bounds__(NTHREADS)
void sky_kernel(const float* __restrict__ rays,
                const int* __restrict__ mask,
                const float* __restrict__ cube,
                const float* __restrict__ cbk,
                float* __restrict__ out)
{
    // Only the thread-divergent gather (cb[best]) uses shared; everything
    // warp-uniform reads from __constant__ (uniform port, off L1tex).
    __shared__ float sCB[NCB*FEAT];
    const int tid = threadIdx.x;
    for (int i = tid; i < NCB*FEAT; i += NTHREADS) sCB[i] = cbk[i];
    __syncthreads();

    const int pix = blockIdx.x * NTHREADS + tid;
    if (pix >= NPIX) return;

    if (mask[pix] == 0) {
        out[pix]          = 0.f;
        out[NPIX + pix]   = 0.f;
        out[2*NPIX + pix] = 0.f;
        return;
    }

    const float x = rays[3*pix+0], y = rays[3*pix+1], z = rays[3*pix+2];
    const float ax = fabsf(x), ay = fabsf(y), az = fabsf(z);
    const bool is_x = (ax >= ay) && (ax >= az);
    const bool is_y = (!is_x) && (ay >= az);

    int face; float ma, u, v;
    if (is_x)       { face = (x >= 0.f) ? 0 : 1; ma = ax; u = (x >= 0.f) ? -z : z; v = -y; }
    else if (is_y)  { face = (y >= 0.f) ? 2 : 3; ma = ay; u = x; v = (y >= 0.f) ? z : -z; }
    else            { face = (z >= 0.f) ? 4 : 5; ma = az; u = (z >= 0.f) ? x : -x; v = -y; }

    const float denom = ma + 1e-9f;
    const float sC = (u/denom + 1.f) * 0.5f * (float)RES - 0.5f;
    const float tC = (v/denom + 1.f) * 0.5f * (float)RES - 0.5f;
    const float fs = floorf(sC), ft = floorf(tC);
    const float fx = sC - fs, fy = tC - ft;
    int x0 = (int)fs; x0 = max(0, min(x0, RES-1));
    const int x1 = min(x0+1, RES-1);
    int y0 = (int)ft; y0 = max(0, min(y0, RES-1));
    const int y1 = min(y0+1, RES-1);

    const float* __restrict__ fb = cube + (size_t)face * (size_t)(RES*RES*FEAT);

    float feat[FEAT], tmp[FEAT], bot[FEAT];
    load12(fb + ((size_t)y0*RES + x0)*FEAT, feat);
    load12(fb + ((size_t)y0*RES + x1)*FEAT, tmp);
    #pragma unroll
    for (int k = 0; k < FEAT; k++) feat[k] = feat[k]*(1.f-fx) + tmp[k]*fx;
    load12(fb + ((size_t)y1*RES + x0)*FEAT, bot);
    load12(fb + ((size_t)y1*RES + x1)*FEAT, tmp);
    #pragma unroll
    for (int k = 0; k < FEAT; k++) bot[k] = bot[k]*(1.f-fx) + tmp[k]*fx;
    #pragma unroll
    for (int k = 0; k < FEAT; k++) feat[k] = feat[k]*(1.f-fy) + bot[k]*fy;

    // nearest codebook (first-min-wins to match jnp.argmin)
    float f2 = 0.f;
    #pragma unroll
    for (int k = 0; k < FEAT; k++) f2 += feat[k]*feat[k];
    int best = 0;
    float bestd = 3.4e38f;
    #pragma unroll 4
    for (int c = 0; c < NCB; c++) {
        float dot = 0.f;
        #pragma unroll
        for (int k = 0; k < FEAT; k++) dot += feat[k]*cCB[c*FEAT + k];
        const float d2 = f2 - 2.f*dot + cC2[c];
        if (d2 < bestd) { bestd = d2; best = c; }
    }

    // straight-through: q = cb[best] (divergent gather -> shared)
    float in[15];
    #pragma unroll
    for (int k = 0; k < FEAT; k++) in[k] = sCB[best*FEAT + k];
    in[12] = x; in[13] = y; in[14] = z;

    // MLP layer 1: 15 -> 32, relu
    float h[32];
    #pragma unroll
    for (int j = 0; j < 32; j++) h[j] = cB1[j];
    #pragma unroll
    for (int k = 0; k < 15; k++) {
        const float iv = in[k];
        #pragma unroll
        for (int j = 0; j < 32; j++) h[j] += iv * cW1[k*32 + j];
    }
    #pragma unroll
    for (int j = 0; j < 32; j++) h[j] = fmaxf(h[j], 0.f);

    // MLP layer 2: 32 -> 32, relu
    float h2[32];
    #pragma unroll
    for (int j = 0; j < 32; j++) h2[j] = cB2[j];
    #pragma unroll
    for (int k = 0; k < 32; k++) {
        const float iv = h[k];
        #pragma unroll
        for (int j = 0; j < 32; j++) h2[j] += iv * cW2[k*32 + j];
    }
    #pragma unroll
    for (int j = 0; j < 32; j++) h2[j] = fmaxf(h2[j], 0.f);

    // MLP layer 3: 32 -> 3, sigmoid
    float r[3];
    #pragma unroll
    for (int c = 0; c < 3; c++) r[c] = cB3[c];
    #pragma unroll
    for (int k = 0; k < 32; k++) {
        const float iv = h2[k];
        #pragma unroll
        for (int c = 0; c < 3; c++) r[c] += iv * cW3[k*3 + c];
    }
    #pragma unroll
    for (int c = 0; c < 3; c++) {
        float s = 1.f / (1.f + expf(-r[c]));
        s = fminf(fmaxf(s, 0.f), 1.f);
        out[c*NPIX + pix] = s;
    }
}

extern "C" void kernel_launch(void* const* d_in, const int* in_sizes, int n_in,
                              void* d_out, int out_size)
{
    const float* rays = (const float*)d_in[0];
    const int*   mask = (const int*)d_in[1];
    const float* cube = (const float*)d_in[2];
    const float* cbk  = (const float*)d_in[3];
    const float* W1   = (const float*)d_in[4];
    const float* b1   = (const float*)d_in[5];
    const float* W2   = (const float*)d_in[6];
    const float* b2   = (const float*)d_in[7];
    const float* W3   = (const float*)d_in[8];
    const float* b3   = (const float*)d_in[9];
    float* out = (float*)d_out;

    // Fill constant memory (graph-capturable D2D memcpy nodes)
    cudaMemcpyToSymbolAsync(cW1, W1, 15*32*sizeof(float), 0, cudaMemcpyDeviceToDevice, 0);
    cudaMemcpyToSymbolAsync(cB1, b1, 32*sizeof(float),    0, cudaMemcpyDeviceToDevice, 0);
    cudaMemcpyToSymbolAsync(cW2, W2, 32*32*sizeof(float), 0, cudaMemcpyDeviceToDevice, 0);
    cudaMemcpyToSymbolAsync(cB2, b2, 32*sizeof(float),    0, cudaMemcpyDeviceToDevice, 0);
    cudaMemcpyToSymbolAsync(cW3, W3, 32*3*sizeof(float),  0, cudaMemcpyDeviceToDevice, 0);
    cudaMemcpyToSymbolAsync(cB3, b3, 3*sizeof(float),     0, cudaMemcpyDeviceToDevice, 0);
    cudaMemcpyToSymbolAsync(cCB, cbk, NCB*FEAT*sizeof(float), 0, cudaMemcpyDeviceToDevice, 0);

    // Precompute ||cb||^2 then copy into constant
    c2_kernel<<<1, 32>>>(cbk);
    float* c2_ptr = nullptr;
    cudaGetSymbolAddress((void**)&c2_ptr, g_c2);
    cudaMemcpyToSymbolAsync(cC2, c2_ptr, NCB*sizeof(float), 0, cudaMemcpyDeviceToDevice, 0);

    const int blocks = (NPIX + NTHREADS - 1) / NTHREADS;
    sky_kernel<<<blocks, NTHREADS>>>(rays, mask, cube, cbk, out);
}

// round 4
// speedup vs baseline: 1.7063x; 1.2269x over previous
#include <cuda_runtime.h>
#include <cuda_bf16.h>

#define RES   1024
#define FEAT  12
#define NCB   32
#define HIMG  1080
#define WIMG  1920
#define NPIX  (HIMG*WIMG)
#define NTHREADS 256

__constant__ float cW1[15*32];
__constant__ float cB1[32];
__constant__ float cW2[32*32];
__constant__ float cB2[32];
__constant__ float cW3[32*3];
__constant__ float cB3[3];
__constant__ float cCB[NCB*FEAT];
__constant__ float cC2[NCB];

__device__ float g_c2[NCB];
__device__ int   g_count;
__device__ int   g_idx[NPIX];

__global__ void c2_kernel(const float* __restrict__ cbk) {
    int c = threadIdx.x;
    if (c < NCB) {
        float a = 0.f;
        #pragma unroll
        for (int k = 0; k < FEAT; k++) { float v = cbk[c*FEAT + k]; a += v*v; }
        g_c2[c] = a;
    }
}

__global__ void reset_kernel() { g_count = 0; }

// Compact active pixel indices; write zeros for masked pixels.
__global__ __launch_bounds__(NTHREADS)
void compact_kernel(const int* __restrict__ mask, float* __restrict__ out)
{
    const int pix = blockIdx.x * NTHREADS + threadIdx.x;
    bool active = false;
    if (pix < NPIX) active = (mask[pix] != 0);

    if (pix < NPIX && !active) {
        out[pix]          = 0.f;
        out[NPIX + pix]   = 0.f;
        out[2*NPIX + pix] = 0.f;
    }

    const unsigned bal = __ballot_sync(0xFFFFFFFFu, active);
    const int lane = threadIdx.x & 31;
    const int cnt  = __popc(bal);
    int base = 0;
    if (lane == 0 && cnt) base = atomicAdd(&g_count, cnt);
    base = __shfl_sync(0xFFFFFFFFu, base, 0);
    if (active) {
        const int rank = __popc(bal & ((1u << lane) - 1u));
        g_idx[base + rank] = pix;
    }
}

__device__ __forceinline__ void load12(const float* __restrict__ p, float* dst) {
    float4 a = *(const float4*)(p);
    float4 b = *(const float4*)(p + 4);
    float4 c = *(const float4*)(p + 8);
    dst[0]=a.x; dst[1]=a.y; dst[2]=a.z;  dst[3]=a.w;
    dst[4]=b.x; dst[5]=b.y; dst[6]=b.z;  dst[7]=b.w;
    dst[8]=c.x; dst[9]=c.y; dst[10]=c.z; dst[11]=c.w;
}

__global__ __launch_bounds__(NTHREADS)
void sky_kernel(const float* __restrict__ rays,
                const float* __restrict__ cube,
                const float* __restrict__ cbk,
                float* __restrict__ out)
{
    __shared__ float sCB[NCB*FEAT];
    const int tid = threadIdx.x;
    for (int i = tid; i < NCB*FEAT; i += NTHREADS) sCB[i] = cbk[i];
    __syncthreads();

    const int i = blockIdx.x * NTHREADS + tid;
    if (i >= g_count) return;
    const int pix = g_idx[i];

    const float x = rays[3*pix+0], y = rays[3*pix+1], z = rays[3*pix+2];
    const float ax = fabsf(x), ay = fabsf(y), az = fabsf(z);
    const bool is_x = (ax >= ay) && (ax >= az);
    const bool is_y = (!is_x) && (ay >= az);

    int face; float ma, u, v;
    if (is_x)       { face = (x >= 0.f) ? 0 : 1; ma = ax; u = (x >= 0.f) ? -z : z; v = -y; }
    else if (is_y)  { face = (y >= 0.f) ? 2 : 3; ma = ay; u = x; v = (y >= 0.f) ? z : -z; }
    else            { face = (z >= 0.f) ? 4 : 5; ma = az; u = (z >= 0.f) ? x : -x; v = -y; }

    const float inv = __fdividef(1.f, ma + 1e-9f);
    const float sC = (u*inv + 1.f) * 0.5f * (float)RES - 0.5f;
    const float tC = (v*inv + 1.f) * 0.5f * (float)RES - 0.5f;
    const float fs = floorf(sC), ft = floorf(tC);
    const float fx = sC - fs, fy = tC - ft;
    int x0 = (int)fs; x0 = max(0, min(x0, RES-1));
    const int x1 = min(x0+1, RES-1);
    int y0 = (int)ft; y0 = max(0, min(y0, RES-1));
    const int y1 = min(y0+1, RES-1);

    const float* __restrict__ fb = cube + (size_t)face * (size_t)(RES*RES*FEAT);

    float feat[FEAT], tmp[FEAT], bot[FEAT];
    load12(fb + ((size_t)y0*RES + x0)*FEAT, feat);
    load12(fb + ((size_t)y0*RES + x1)*FEAT, tmp);
    #pragma unroll
    for (int k = 0; k < FEAT; k++) feat[k] = feat[k]*(1.f-fx) + tmp[k]*fx;
    load12(fb + ((size_t)y1*RES + x0)*FEAT, bot);
    load12(fb + ((size_t)y1*RES + x1)*FEAT, tmp);
    #pragma unroll
    for (int k = 0; k < FEAT; k++) bot[k] = bot[k]*(1.f-fx) + tmp[k]*fx;
    #pragma unroll
    for (int k = 0; k < FEAT; k++) feat[k] = feat[k]*(1.f-fy) + bot[k]*fy;

    // nearest codebook (first-min-wins to match jnp.argmin)
    float f2 = 0.f;
    #pragma unroll
    for (int k = 0; k < FEAT; k++) f2 += feat[k]*feat[k];
    int best = 0;
    float bestd = 3.4e38f;
    #pragma unroll 4
    for (int c = 0; c < NCB; c++) {
        float dot = 0.f;
        #pragma unroll
        for (int k = 0; k < FEAT; k++) dot += feat[k]*cCB[c*FEAT + k];
        const float d2 = f2 - 2.f*dot + cC2[c];
        if (d2 < bestd) { bestd = d2; best = c; }
    }

    // straight-through: q = cb[best] (divergent gather -> shared)
    float in[15];
    #pragma unroll
    for (int k = 0; k < FEAT; k++) in[k] = sCB[best*FEAT + k];
    in[12] = x; in[13] = y; in[14] = z;

    // MLP layer 1: 15 -> 32, relu
    float h[32];
    #pragma unroll
    for (int j = 0; j < 32; j++) h[j] = cB1[j];
    #pragma unroll
    for (int k = 0; k < 15; k++) {
        const float iv = in[k];
        #pragma unroll
        for (int j = 0; j < 32; j++) h[j] += iv * cW1[k*32 + j];
    }
    #pragma unroll
    for (int j = 0; j < 32; j++) h[j] = fmaxf(h[j], 0.f);

    // MLP layer 2: 32 -> 32, relu
    float h2[32];
    #pragma unroll
    for (int j = 0; j < 32; j++) h2[j] = cB2[j];
    #pragma unroll
    for (int k = 0; k < 32; k++) {
        const float iv = h[k];
        #pragma unroll
        for (int j = 0; j < 32; j++) h2[j] += iv * cW2[k*32 + j];
    }
    #pragma unroll
    for (int j = 0; j < 32; j++) h2[j] = fmaxf(h2[j], 0.f);

    // MLP layer 3: 32 -> 3, sigmoid
    float r[3];
    #pragma unroll
    for (int c = 0; c < 3; c++) r[c] = cB3[c];
    #pragma unroll
    for (int k = 0; k < 32; k++) {
        const float iv = h2[k];
        #pragma unroll
        for (int c = 0; c < 3; c++) r[c] += iv * cW3[k*3 + c];
    }
    #pragma unroll
    for (int c = 0; c < 3; c++) {
        float s = __fdividef(1.f, 1.f + __expf(-r[c]));
        s = fminf(fmaxf(s, 0.f), 1.f);
        out[c*NPIX + pix] = s;
    }
}

extern "C" void kernel_launch(void* const* d_in, const int* in_sizes, int n_in,
                              void* d_out, int out_size)
{
    const float* rays = (const float*)d_in[0];
    const int*   mask = (const int*)d_in[1];
    const float* cube = (const float*)d_in[2];
    const float* cbk  = (const float*)d_in[3];
    const float* W1   = (const float*)d_in[4];
    const float* b1   = (const float*)d_in[5];
    const float* W2   = (const float*)d_in[6];
    const float* b2   = (const float*)d_in[7];
    const float* W3   = (const float*)d_in[8];
    const float* b3   = (const float*)d_in[9];
    float* out = (float*)d_out;

    cudaMemcpyToSymbolAsync(cW1, W1, 15*32*sizeof(float), 0, cudaMemcpyDeviceToDevice, 0);
    cudaMemcpyToSymbolAsync(cB1, b1, 32*sizeof(float),    0, cudaMemcpyDeviceToDevice, 0);
    cudaMemcpyToSymbolAsync(cW2, W2, 32*32*sizeof(float), 0, cudaMemcpyDeviceToDevice, 0);
    cudaMemcpyToSymbolAsync(cB2, b2, 32*sizeof(float),    0, cudaMemcpyDeviceToDevice, 0);
    cudaMemcpyToSymbolAsync(cW3, W3, 32*3*sizeof(float),  0, cudaMemcpyDeviceToDevice, 0);
    cudaMemcpyToSymbolAsync(cB3, b3, 3*sizeof(float),     0, cudaMemcpyDeviceToDevice, 0);
    cudaMemcpyToSymbolAsync(cCB, cbk, NCB*FEAT*sizeof(float), 0, cudaMemcpyDeviceToDevice, 0);

    c2_kernel<<<1, 32>>>(cbk);
    float* c2_ptr = nullptr;
    cudaGetSymbolAddress((void**)&c2_ptr, g_c2);
    cudaMemcpyToSymbolAsync(cC2, c2_ptr, NCB*sizeof(float), 0, cudaMemcpyDeviceToDevice, 0);

    const int blocks = (NPIX + NTHREADS - 1) / NTHREADS;
    reset_kernel<<<1, 1>>>();
    compact_kernel<<<blocks, NTHREADS>>>(mask, out);
    sky_kernel<<<blocks, NTHREADS>>>(rays, cube, cbk, out);
}

// round 5
// speedup vs baseline: 1.8009x; 1.0554x over previous
#include <cuda_runtime.h>
#include <cuda_bf16.h>

#define RES   1024
#define FEAT  12
#define NCB   32
#define HIMG  1080
#define WIMG  1920
#define NPIX  (HIMG*WIMG)
#define NT    256

typedef unsigned long long ull;

// ---------------- packed f32x2 helpers ----------------
__device__ __forceinline__ ull pack2(float lo, float hi) {
    ull r; asm("mov.b64 %0, {%1, %2};" : "=l"(r) : "f"(lo), "f"(hi)); return r;
}
__device__ __forceinline__ void unpack2(ull v, float& lo, float& hi) {
    asm("mov.b64 {%0, %1}, %2;" : "=f"(lo), "=f"(hi) : "l"(v));
}
__device__ __forceinline__ ull fma2(ull a, ull b, ull c) {
    ull d; asm("fma.rn.f32x2 %0, %1, %2, %3;" : "=l"(d) : "l"(a), "l"(b), "l"(c)); return d;
}
__device__ __forceinline__ ull mul2(ull a, ull b) {
    ull d; asm("mul.rn.f32x2 %0, %1, %2;" : "=l"(d) : "l"(a), "l"(b)); return d;
}

// ---------------- constants (single struct, one memcpy) ----------------
struct Consts {
    float W1[15*32];   // row-major [k][j]
    float B1[32];
    float W2[32*32];   // row-major [k][j]
    float B2[32];
    float W3T[3*32];   // TRANSPOSED: [c][k]
    float B3[3];
    float pad;
    float CB[NCB*FEAT];
    float C2[NCB];
};
__device__ Consts g_stage;
__constant__ Consts cC;
__device__ int g_count;
__device__ int g_idx[NPIX];

__global__ void setup_kernel(const float* __restrict__ W1, const float* __restrict__ b1,
                             const float* __restrict__ W2, const float* __restrict__ b2,
                             const float* __restrict__ W3, const float* __restrict__ b3,
                             const float* __restrict__ cbk)
{
    const int t = threadIdx.x;     // 1024 threads
    if (t == 0) { g_count = 0; g_stage.pad = 0.f; }
    if (t < 15*32) g_stage.W1[t] = W1[t];
    if (t < 32)    { g_stage.B1[t] = b1[t]; g_stage.B2[t] = b2[t]; }
    g_stage.W2[t] = W2[t];         // exactly 1024
    if (t < 96)    { int c = t / 32, k = t % 32; g_stage.W3T[t] = W3[k*3 + c]; }
    if (t < 3)     g_stage.B3[t] = b3[t];
    if (t < NCB*FEAT) g_stage.CB[t] = cbk[t];
    if (t < NCB) {
        float a = 0.f;
        #pragma unroll
        for (int k = 0; k < FEAT; k++) { float v = cbk[t*FEAT + k]; a += v*v; }
        g_stage.C2[t] = a;
    }
}

// ---------------- compaction ----------------
__global__ __launch_bounds__(NT)
void compact_kernel(const int* __restrict__ mask, float* __restrict__ out)
{
    const int pix = blockIdx.x * NT + threadIdx.x;
    bool active = false;
    if (pix < NPIX) active = (mask[pix] != 0);

    if (pix < NPIX && !active) {
        out[pix]          = 0.f;
        out[NPIX + pix]   = 0.f;
        out[2*NPIX + pix] = 0.f;
    }

    const unsigned bal = __ballot_sync(0xFFFFFFFFu, active);
    const int lane = threadIdx.x & 31;
    const int cnt  = __popc(bal);
    int base = 0;
    if (lane == 0 && cnt) base = atomicAdd(&g_count, cnt);
    base = __shfl_sync(0xFFFFFFFFu, base, 0);
    if (active) {
        const int rank = __popc(bal & ((1u << lane) - 1u));
        g_idx[base + rank] = pix;
    }
}

// load 12 floats (one texel) as 6 packed f32x2 (3x LDG.128; 48B stride keeps 16B alignment)
__device__ __forceinline__ void load12p(const float* __restrict__ p, ull* dst) {
    ulonglong2 a = *(const ulonglong2*)(p);
    ulonglong2 b = *(const ulonglong2*)(p + 4);
    ulonglong2 c = *(const ulonglong2*)(p + 8);
    dst[0] = a.x; dst[1] = a.y;
    dst[2] = b.x; dst[3] = b.y;
    dst[4] = c.x; dst[5] = c.y;
}

__global__ __launch_bounds__(NT)
void sky_kernel(const float* __restrict__ rays,
                const float* __restrict__ cube,
                float* __restrict__ out)
{
    __shared__ float sCB[NCB*FEAT];    // divergent gather target
    const int tid = threadIdx.x;
    for (int j = tid; j < NCB*FEAT; j += NT) sCB[j] = cC.CB[j];
    __syncthreads();

    const int i = blockIdx.x * NT + tid;
    if (i >= g_count) return;
    const int pix = g_idx[i];

    const float x = rays[3*pix+0], y = rays[3*pix+1], z = rays[3*pix+2];
    const float ax = fabsf(x), ay = fabsf(y), az = fabsf(z);
    const bool is_x = (ax >= ay) && (ax >= az);
    const bool is_y = (!is_x) && (ay >= az);

    int face; float ma, u, v;
    if (is_x)       { face = (x >= 0.f) ? 0 : 1; ma = ax; u = (x >= 0.f) ? -z : z; v = -y; }
    else if (is_y)  { face = (y >= 0.f) ? 2 : 3; ma = ay; u = x; v = (y >= 0.f) ? z : -z; }
    else            { face = (z >= 0.f) ? 4 : 5; ma = az; u = (z >= 0.f) ? x : -x; v = -y; }

    const float inv = 1.0f / (ma + 1e-9f);   // precise: texel selection must match ref
    const float sC = (u*inv + 1.f) * 0.5f * (float)RES - 0.5f;
    const float tC = (v*inv + 1.f) * 0.5f * (float)RES - 0.5f;
    const float fs = floorf(sC), ft = floorf(tC);
    const float fx = sC - fs, fy = tC - ft;
    int x0 = (int)fs; x0 = max(0, min(x0, RES-1));
    const int x1 = min(x0+1, RES-1);
    int y0 = (int)ft; y0 = max(0, min(y0, RES-1));
    const int y1 = min(y0+1, RES-1);

    const float* __restrict__ fb = cube + (size_t)face * (size_t)(RES*RES*FEAT);

    ull t00[6], t01[6], t10[6], t11[6];
    load12p(fb + ((size_t)y0*RES + x0)*FEAT, t00);
    load12p(fb + ((size_t)y0*RES + x1)*FEAT, t01);
    load12p(fb + ((size_t)y1*RES + x0)*FEAT, t10);
    load12p(fb + ((size_t)y1*RES + x1)*FEAT, t11);

    const ull fx2  = pack2(fx, fx),        fy2  = pack2(fy, fy);
    const ull ofx2 = pack2(1.f-fx, 1.f-fx), ofy2 = pack2(1.f-fy, 1.f-fy);

    ull feat2[6];
    #pragma unroll
    for (int j = 0; j < 6; j++) {
        ull top = fma2(t01[j], fx2, mul2(t00[j], ofx2));
        ull bot = fma2(t11[j], fx2, mul2(t10[j], ofx2));
        feat2[j] = fma2(bot, fy2, mul2(top, ofy2));
    }

    // nearest codebook: argmin_c (-2*dot + ||cb_c||^2)  (f2 constant, drops out)
    const ull* __restrict__ cCB2 = (const ull*)cC.CB;
    int best = 0;
    float bestd = 3.4e38f;
    #pragma unroll 4
    for (int c = 0; c < NCB; c++) {
        ull acc = mul2(feat2[0], cCB2[c*6 + 0]);
        #pragma unroll
        for (int k = 1; k < 6; k++) acc = fma2(feat2[k], cCB2[c*6 + k], acc);
        float lo, hi; unpack2(acc, lo, hi);
        const float d2 = fmaf(-2.f, lo + hi, cC.C2[c]);
        if (d2 < bestd) { bestd = d2; best = c; }
    }

    // q = cb[best] (divergent gather from shared, 64-bit LDS)
    float in[15];
    {
        const ull* __restrict__ sCB2 = (const ull*)sCB;
        #pragma unroll
        for (int j = 0; j < 6; j++) {
            ull q = sCB2[best*6 + j];
            unpack2(q, in[2*j], in[2*j+1]);
        }
    }
    in[12] = x; in[13] = y; in[14] = z;

    const ull* __restrict__ W1p  = (const ull*)cC.W1;
    const ull* __restrict__ W2p  = (const ull*)cC.W2;
    const ull* __restrict__ W3Tp = (const ull*)cC.W3T;
    const ull* __restrict__ B1p  = (const ull*)cC.B1;
    const ull* __restrict__ B2p  = (const ull*)cC.B2;

    // layer 1: 15 -> 32, relu (packed pairs of outputs)
    ull acc[16];
    #pragma unroll
    for (int j = 0; j < 16; j++) acc[j] = B1p[j];
    #pragma unroll
    for (int k = 0; k < 15; k++) {
        const ull iv2 = pack2(in[k], in[k]);
        #pragma unroll
        for (int j = 0; j < 16; j++) acc[j] = fma2(iv2, W1p[k*16 + j], acc[j]);
    }
    float h[32];
    #pragma unroll
    for (int j = 0; j < 16; j++) {
        float a, b; unpack2(acc[j], a, b);
        h[2*j]   = fmaxf(a, 0.f);
        h[2*j+1] = fmaxf(b, 0.f);
    }

    // layer 2: 32 -> 32, relu (packed)
    #pragma unroll
    for (int j = 0; j < 16; j++) acc[j] = B2p[j];
    #pragma unroll
    for (int k = 0; k < 32; k++) {
        const ull iv2 = pack2(h[k], h[k]);
        #pragma unroll
        for (int j = 0; j < 16; j++) acc[j] = fma2(iv2, W2p[k*16 + j], acc[j]);
    }
    ull h2p[16];
    #pragma unroll
    for (int j = 0; j < 16; j++) {
        float a, b; unpack2(acc[j], a, b);
        h2p[j] = pack2(fmaxf(a, 0.f), fmaxf(b, 0.f));
    }

    // layer 3: 32 -> 3 as packed dot products over transposed weights, sigmoid
    #pragma unroll
    for (int c = 0; c < 3; c++) {
        ull a2 = mul2(h2p[0], W3Tp[c*16 + 0]);
        #pragma unroll
        for (int k = 1; k < 16; k++) a2 = fma2(h2p[k], W3Tp[c*16 + k], a2);
        float lo, hi; unpack2(a2, lo, hi);
        const float r = lo + hi + cC.B3[c];
        float s = __fdividef(1.f, 1.f + __expf(-r));
        s = fminf(fmaxf(s, 0.f), 1.f);
        out[c*NPIX + pix] = s;
    }
}

extern "C" void kernel_launch(void* const* d_in, const int* in_sizes, int n_in,
                              void* d_out, int out_size)
{
    const float* rays = (const float*)d_in[0];
    const int*   mask = (const int*)d_in[1];
    const float* cube = (const float*)d_in[2];
    const float* cbk  = (const float*)d_in[3];
    const float* W1   = (const float*)d_in[4];
    const float* b1   = (const float*)d_in[5];
    const float* W2   = (const float*)d_in[6];
    const float* b2   = (const float*)d_in[7];
    const float* W3   = (const float*)d_in[8];
    const float* b3   = (const float*)d_in[9];
    float* out = (float*)d_out;

    setup_kernel<<<1, 1024>>>(W1, b1, W2, b2, W3, b3, cbk);

    void* stage_ptr = nullptr;
    cudaGetSymbolAddress(&stage_ptr, g_stage);
    cudaMemcpyToSymbolAsync(cC, stage_ptr, sizeof(Consts), 0, cudaMemcpyDeviceToDevice, 0);

    const int blocks = (NPIX + NT - 1) / NT;
    compact_kernel<<<blocks, NT>>>(mask, out);
    sky_kernel<<<blocks, NT>>>(rays, cube, out);
}

// round 6
// speedup vs baseline: 1.8386x; 1.0210x over previous
#include <cuda_runtime.h>
#include <cuda_bf16.h>

#define RES   1024
#define FEAT  12
#define NCB   32
#define HIMG  1080
#define WIMG  1920
#define NPIX  (HIMG*WIMG)       // 2,073,600 = 4050 * 512
#define NT    256
#define PIX_PER_BLOCK 512

struct Consts {
    float W1[15*32];   // [k][j]
    float B1[32];
    float W2[32*32];   // [k][j]
    float B2[32];
    float W3[32*3];    // [k][c]
    float B3[3];
    float pad;
    float CB[NCB*FEAT];
    float C2[NCB];
};
__device__ Consts g_stage;
__constant__ Consts cC;

__global__ void setup_kernel(const float* __restrict__ W1, const float* __restrict__ b1,
                             const float* __restrict__ W2, const float* __restrict__ b2,
                             const float* __restrict__ W3, const float* __restrict__ b3,
                             const float* __restrict__ cbk)
{
    const int t = threadIdx.x;     // 1024 threads
    if (t == 0) g_stage.pad = 0.f;
    if (t < 15*32) g_stage.W1[t] = W1[t];
    if (t < 32)    { g_stage.B1[t] = b1[t]; g_stage.B2[t] = b2[t]; }
    g_stage.W2[t] = W2[t];         // exactly 1024
    if (t < 96)    g_stage.W3[t] = W3[t];
    if (t < 3)     g_stage.B3[t] = b3[t];
    if (t < NCB*FEAT) g_stage.CB[t] = cbk[t];
    if (t < NCB) {
        float a = 0.f;
        #pragma unroll
        for (int k = 0; k < FEAT; k++) { float v = cbk[t*FEAT + k]; a += v*v; }
        g_stage.C2[t] = a;
    }
}

__device__ __forceinline__ void load12(const float* __restrict__ p, float* dst) {
    float4 a = *(const float4*)(p);
    float4 b = *(const float4*)(p + 4);
    float4 c = *(const float4*)(p + 8);
    dst[0]=a.x; dst[1]=a.y; dst[2]=a.z;  dst[3]=a.w;
    dst[4]=b.x; dst[5]=b.y; dst[6]=b.z;  dst[7]=b.w;
    dst[8]=c.x; dst[9]=c.y; dst[10]=c.z; dst[11]=c.w;
}

__global__ __launch_bounds__(NT)
void sky_kernel(const float* __restrict__ rays,
                const int* __restrict__ mask,
                const float* __restrict__ cube,
                float* __restrict__ out)
{
    __shared__ float sCB[NCB*FEAT];   // divergent cb[best] gather target
    __shared__ int   sIdx[PIX_PER_BLOCK];
    __shared__ int   sCnt;

    const int tid  = threadIdx.x;
    const int lane = tid & 31;
    for (int j = tid; j < NCB*FEAT; j += NT) sCB[j] = cC.CB[j];
    if (tid == 0) sCnt = 0;
    __syncthreads();

    // ---- phase 1: block-local compaction over 512 pixels + zero fills ----
    const int base = blockIdx.x * PIX_PER_BLOCK;
    #pragma unroll
    for (int r = 0; r < PIX_PER_BLOCK / NT; r++) {
        const int pix = base + r * NT + tid;
        const bool active = (mask[pix] != 0);
        if (!active) {
            out[pix]          = 0.f;
            out[NPIX + pix]   = 0.f;
            out[2*NPIX + pix] = 0.f;
        }
        const unsigned bal = __ballot_sync(0xFFFFFFFFu, active);
        int wbase = 0;
        if (lane == 0) wbase = atomicAdd(&sCnt, __popc(bal));
        wbase = __shfl_sync(0xFFFFFFFFu, wbase, 0);
        if (active) sIdx[wbase + __popc(bal & ((1u << lane) - 1u))] = pix;
    }
    __syncthreads();
    const int cnt = sCnt;

    // ---- phase 2: process compacted pixels with full warps ----
    for (int i = tid; i < cnt; i += NT) {
        const int pix = sIdx[i];

        const float x = rays[3*pix+0], y = rays[3*pix+1], z = rays[3*pix+2];
        const float ax = fabsf(x), ay = fabsf(y), az = fabsf(z);
        const bool is_x = (ax >= ay) && (ax >= az);
        const bool is_y = (!is_x) && (ay >= az);

        int face; float ma, u, v;
        if (is_x)      { face = (x >= 0.f) ? 0 : 1; ma = ax; u = (x >= 0.f) ? -z : z; v = -y; }
        else if (is_y) { face = (y >= 0.f) ? 2 : 3; ma = ay; u = x; v = (y >= 0.f) ? z : -z; }
        else           { face = (z >= 0.f) ? 4 : 5; ma = az; u = (z >= 0.f) ? x : -x; v = -y; }

        const float inv = 1.0f / (ma + 1e-9f);
        const float sc = (u*inv + 1.f) * 0.5f * (float)RES - 0.5f;
        const float tc = (v*inv + 1.f) * 0.5f * (float)RES - 0.5f;
        const float fs = floorf(sc), ft = floorf(tc);
        const float fx = sc - fs, fy = tc - ft;
        int x0 = (int)fs; x0 = max(0, min(x0, RES-1));
        const int x1 = min(x0+1, RES-1);
        int y0 = (int)ft; y0 = max(0, min(y0, RES-1));
        const int y1 = min(y0+1, RES-1);

        const float* __restrict__ fb = cube + (size_t)face * (size_t)(RES*RES*FEAT);

        float feat[FEAT], tmp[FEAT], bot[FEAT];
        load12(fb + ((size_t)y0*RES + x0)*FEAT, feat);
        load12(fb + ((size_t)y0*RES + x1)*FEAT, tmp);
        #pragma unroll
        for (int k = 0; k < FEAT; k++) feat[k] = feat[k]*(1.f-fx) + tmp[k]*fx;
        load12(fb + ((size_t)y1*RES + x0)*FEAT, bot);
        load12(fb + ((size_t)y1*RES + x1)*FEAT, tmp);
        #pragma unroll
        for (int k = 0; k < FEAT; k++) bot[k] = bot[k]*(1.f-fx) + tmp[k]*fx;
        #pragma unroll
        for (int k = 0; k < FEAT; k++) feat[k] = feat[k]*(1.f-fy) + bot[k]*fy;

        // nearest codebook — exact round-3 arithmetic (first-min-wins)
        float f2 = 0.f;
        #pragma unroll
        for (int k = 0; k < FEAT; k++) f2 += feat[k]*feat[k];
        int best = 0;
        float bestd = 3.4e38f;
        #pragma unroll 4
        for (int c = 0; c < NCB; c++) {
            float dot = 0.f;
            #pragma unroll
            for (int k = 0; k < FEAT; k++) dot += feat[k]*cC.CB[c*FEAT + k];
            const float d2 = f2 - 2.f*dot + cC.C2[c];
            if (d2 < bestd) { bestd = d2; best = c; }
        }

        float in[15];
        #pragma unroll
        for (int k = 0; k < FEAT; k++) in[k] = sCB[best*FEAT + k];
        in[12] = x; in[13] = y; in[14] = z;

        // layer 1: 15 -> 32, relu
        float h[32];
        #pragma unroll
        for (int j = 0; j < 32; j++) h[j] = cC.B1[j];
        #pragma unroll
        for (int k = 0; k < 15; k++) {
            const float iv = in[k];
            #pragma unroll
            for (int j = 0; j < 32; j++) h[j] += iv * cC.W1[k*32 + j];
        }
        #pragma unroll
        for (int j = 0; j < 32; j++) h[j] = fmaxf(h[j], 0.f);

        // layer 2: 32 -> 32, relu
        float h2[32];
        #pragma unroll
        for (int j = 0; j < 32; j++) h2[j] = cC.B2[j];
        #pragma unroll
        for (int k = 0; k < 32; k++) {
            const float iv = h[k];
            #pragma unroll
            for (int j = 0; j < 32; j++) h2[j] += iv * cC.W2[k*32 + j];
        }
        #pragma unroll
        for (int j = 0; j < 32; j++) h2[j] = fmaxf(h2[j], 0.f);

        // layer 3: 32 -> 3, sigmoid
        float r0 = cC.B3[0], r1 = cC.B3[1], r2 = cC.B3[2];
        #pragma unroll
        for (int k = 0; k < 32; k++) {
            const float iv = h2[k];
            r0 += iv * cC.W3[k*3 + 0];
            r1 += iv * cC.W3[k*3 + 1];
            r2 += iv * cC.W3[k*3 + 2];
        }
        float s0 = 1.f / (1.f + expf(-r0));
        float s1 = 1.f / (1.f + expf(-r1));
        float s2 = 1.f / (1.f + expf(-r2));
        out[pix]          = fminf(fmaxf(s0, 0.f), 1.f);
        out[NPIX + pix]   = fminf(fmaxf(s1, 0.f), 1.f);
        out[2*NPIX + pix] = fminf(fmaxf(s2, 0.f), 1.f);
    }
}

extern "C" void kernel_launch(void* const* d_in, const int* in_sizes, int n_in,
                              void* d_out, int out_size)
{
    const float* rays = (const float*)d_in[0];
    const int*   mask = (const int*)d_in[1];
    const float* cube = (const float*)d_in[2];
    const float* cbk  = (const float*)d_in[3];
    const float* W1   = (const float*)d_in[4];
    const float* b1   = (const float*)d_in[5];
    const float* W2   = (const float*)d_in[6];
    const float* b2   = (const float*)d_in[7];
    const float* W3   = (const float*)d_in[8];
    const float* b3   = (const float*)d_in[9];
    float* out = (float*)d_out;

    setup_kernel<<<1, 1024>>>(W1, b1, W2, b2, W3, b3, cbk);

    void* stage_ptr = nullptr;
    cudaGetSymbolAddress(&stage_ptr, g_stage);
    cudaMemcpyToSymbolAsync(cC, stage_ptr, sizeof(Consts), 0, cudaMemcpyDeviceToDevice, 0);

    sky_kernel<<<NPIX / PIX_PER_BLOCK, NT>>>(rays, mask, cube, out);
}